// round 9
// baseline (speedup 1.0000x reference)
#include <cuda_runtime.h>
#include <cuda_fp16.h>
#include <cstdint>

// ---------------- problem constants ----------------
constexpr int Bq = 4096;
constexpr int Eq = 512;   // K
constexpr int Tq = 32;
constexpr int Hq = 256;
constexpr int ITq = 5;
#define EPSq 1e-6f

// ---------------- fragment-ready scratch ----------------
// A frags: [mtile32 128][ks 32][mfrag 2][lane 32][8 halves]       = 4 MB
// B frags: [tok 32][ks 32][warp 8][fpair 4][lane 32][8 halves]    = 16 MB
__device__ __align__(256) __half g_xa[(size_t)128 * 32 * 2 * 32 * 8];
__device__ __align__(256) __half g_xb[(size_t)32 * 32 * 8 * 4 * 32 * 8];

__device__ __forceinline__ void mma16816(float* d, const uint32_t* a,
                                         const uint32_t* b) {
    asm volatile(
        "mma.sync.aligned.m16n8k16.row.col.f32.f16.f16.f32 "
        "{%0,%1,%2,%3},{%4,%5,%6,%7},{%8,%9},{%0,%1,%2,%3};"
        : "+f"(d[0]), "+f"(d[1]), "+f"(d[2]), "+f"(d[3])
        : "r"(a[0]), "r"(a[1]), "r"(a[2]), "r"(a[3]), "r"(b[0]), "r"(b[1]));
}
#define PF_L1(p) asm volatile("prefetch.global.L1 [%0];" :: "l"(p))

// ---------------- kernel 1: x -> A fragments ----------------
__global__ __launch_bounds__(256)
void convert_a_kernel(const float* __restrict__ x) {
    const int idx   = blockIdx.x * 256 + threadIdx.x;
    const int lane  = idx & 31;
    const int mfrag = (idx >> 5) & 1;
    const int ks    = (idx >> 6) & 31;
    const int mtile = idx >> 11;
    const int r0 = mtile * 32 + mfrag * 16 + (lane >> 2);
    const int c0 = ks * 16 + 2 * (lane & 3);
    const float* xr0 = x + (size_t)r0 * Eq;
    const float* xr1 = xr0 + 8 * Eq;
    __half h[8];
    h[0] = __float2half_rn(xr0[c0]);     h[1] = __float2half_rn(xr0[c0 + 1]);
    h[2] = __float2half_rn(xr1[c0]);     h[3] = __float2half_rn(xr1[c0 + 1]);
    h[4] = __float2half_rn(xr0[c0 + 8]); h[5] = __float2half_rn(xr0[c0 + 9]);
    h[6] = __float2half_rn(xr1[c0 + 8]); h[7] = __float2half_rn(xr1[c0 + 9]);
    reinterpret_cast<uint4*>(g_xa)[idx] = *reinterpret_cast<uint4*>(h);
}

// ---------------- kernel 2: w -> B fragments (paired layout) ----------------
__global__ __launch_bounds__(256)
void convert_b_kernel(const float* __restrict__ w_in,
                      const float* __restrict__ w_val) {
    __shared__ float tile[32][33];
    const int bz = blockIdx.x;
    const int e0 = (bz & 15) * 32;
    const int h0 = ((bz >> 4) & 7) * 32;
    const int z  = bz >> 7;
    const int m  = z >> 5;
    const int t  = z & 31;
    const float* src = (m ? w_val : w_in) + (size_t)t * Eq * Hq;
    const int tx = threadIdx.x & 31;
    const int ty = threadIdx.x >> 5;
    #pragma unroll
    for (int r = ty; r < 32; r += 8)
        tile[r][tx] = src[(size_t)(e0 + r) * Hq + h0 + tx];
    __syncthreads();
    const int lane = threadIdx.x & 31;
    const int f    = (threadIdx.x >> 5) & 3;
    const int ksl  = threadIdx.x >> 7;            // 0/1
    const int ks   = (e0 >> 4) + ksl;
    const int k0   = ksl * 16 + 2 * (lane & 3);
    const int hc   = f * 8 + (lane >> 2);
    const int wp   = h0 >> 5;
    const int fi   = f + m * 4;                   // 0..7
    __half hv[4];
    hv[0] = __float2half_rn(tile[k0][hc]);
    hv[1] = __float2half_rn(tile[k0 + 1][hc]);
    hv[2] = __float2half_rn(tile[k0 + 8][hc]);
    hv[3] = __float2half_rn(tile[k0 + 9][hc]);
    // paired layout: [t][ks][wp][fi>>1][lane] 16B, half (fi&1) selects 8B
    const size_t di = (((((size_t)t * 32 + ks) * 8 + wp) * 4 + (fi >> 1)) * 32
                      + lane) * 2 + (fi & 1);
    reinterpret_cast<uint2*>(g_xb)[di] = *reinterpret_cast<uint2*>(hv);
}

// ---------------- kernel 3: all-LDG register GEMM + fused epilogue ----------
__global__ __launch_bounds__(256, 2)
void gemm_fused_kernel(const float* __restrict__ alphas,
                       const float* __restrict__ scales,
                       const float* __restrict__ gamma,
                       const float* __restrict__ beta,
                       float* __restrict__ out)
{
    __shared__ float red[2][8][32];

    const int tid  = threadIdx.x;
    const int wid  = tid >> 5;
    const int lane = tid & 31;
    const int mtile = blockIdx.x;   // 0..127
    const int tok   = blockIdx.y;   // 0..31
    const int b0    = mtile * 32;

    const uint4* pa = reinterpret_cast<const uint4*>(g_xa)
                    + ((size_t)mtile * 32) * 2 * 32 + lane;
    const uint4* pb = reinterpret_cast<const uint4*>(g_xb)
                    + (((size_t)tok * 32) * 8 + wid) * 4 * 32 + lane;

    float acc[2][8][4];
    #pragma unroll
    for (int i = 0; i < 2; i++)
        #pragma unroll
        for (int j = 0; j < 8; j++)
            #pragma unroll
            for (int k = 0; k < 4; k++) acc[i][j][k] = 0.0f;

    uint4 a0[2], a1[2];
    uint4 bb0[4], bb1[4];

    #define LOAD_A(ks, A) do {                                   \
        A[0] = pa[(size_t)(ks) * 64];                            \
        A[1] = pa[(size_t)(ks) * 64 + 32];                       \
    } while (0)
    #define LOAD_B(ks, BB) do {                                  \
        _Pragma("unroll")                                        \
        for (int j = 0; j < 4; j++)                              \
            BB[j] = pb[(size_t)(ks) * 1024 + j * 32];            \
    } while (0)
    #define DO_MMA(A, BB) do {                                   \
        _Pragma("unroll")                                        \
        for (int mf = 0; mf < 2; mf++)                           \
            _Pragma("unroll")                                    \
            for (int f = 0; f < 8; f++)                          \
                mma16816(acc[mf][f],                             \
                         reinterpret_cast<const uint32_t*>(&A[mf]), \
                         reinterpret_cast<const uint32_t*>(&BB[f >> 1]) + (f & 1) * 2); \
    } while (0)
    #define PREFETCH(ks) do {                                    \
        PF_L1(pa + (size_t)(ks) * 64);                           \
        PF_L1(pa + (size_t)(ks) * 64 + 32);                      \
        _Pragma("unroll")                                        \
        for (int j = 0; j < 4; j++)                              \
            PF_L1(pb + (size_t)(ks) * 1024 + j * 32);            \
    } while (0)

    // warm L1 for the first few chunks
    PREFETCH(2); PREFETCH(3);

    LOAD_A(0, a0); LOAD_B(0, bb0);
    #pragma unroll
    for (int ks = 0; ks < 32; ks += 2) {
        if (ks + 1 < 32) { LOAD_A(ks + 1, a1); LOAD_B(ks + 1, bb1); }
        if (ks + 4 < 32) PREFETCH(ks + 4);
        DO_MMA(a0, bb0);
        if (ks + 2 < 32) { LOAD_A(ks + 2, a0); LOAD_B(ks + 2, bb0); }
        if (ks + 5 < 32) PREFETCH(ks + 5);
        if (ks + 1 < 32) DO_MMA(a1, bb1);
    }

    // ---------------- epilogue (register-resident gating) ----------------
    float xt[2][4][4], vv[2][4][4];
    #pragma unroll
    for (int mf = 0; mf < 2; mf++)
        #pragma unroll
        for (int f = 0; f < 4; f++)
            #pragma unroll
            for (int c = 0; c < 4; c++) {
                xt[mf][f][c] = fmaxf(acc[mf][f][c], 0.0f);
                vv[mf][f][c] = acc[mf][f + 4][c];
            }

    float av[ITq];
    #pragma unroll
    for (int i = 0; i < ITq; i++) av[i] = alphas[tok * ITq + i];

    float2 sc[4], gm[4], bt[4];
    #pragma unroll
    for (int f = 0; f < 4; f++) {
        const int col = wid * 32 + f * 8 + 2 * (lane & 3);
        sc[f] = *reinterpret_cast<const float2*>(scales + tok * Hq + col);
        gm[f] = *reinterpret_cast<const float2*>(gamma  + tok * Hq + col);
        bt[f] = *reinterpret_cast<const float2*>(beta   + tok * Hq + col);
    }

    constexpr float INVH = 1.0f / (float)Hq;
    const int q = lane >> 2;

    #pragma unroll
    for (int it = 0; it < ITq; it++) {
        float plo[2], phi[2];
        #pragma unroll
        for (int mf = 0; mf < 2; mf++) {
            plo[mf] = 0.0f; phi[mf] = 0.0f;
            #pragma unroll
            for (int f = 0; f < 4; f++) {
                plo[mf] += xt[mf][f][0] + xt[mf][f][1];
                phi[mf] += xt[mf][f][2] + xt[mf][f][3];
            }
        }
        #pragma unroll
        for (int off = 1; off <= 2; off <<= 1) {
            #pragma unroll
            for (int mf = 0; mf < 2; mf++) {
                plo[mf] += __shfl_xor_sync(0xffffffffu, plo[mf], off);
                phi[mf] += __shfl_xor_sync(0xffffffffu, phi[mf], off);
            }
        }
        const int buf = it & 1;
        if ((lane & 3) == 0) {
            red[buf][wid][q]      = plo[0];
            red[buf][wid][q + 8]  = phi[0];
            red[buf][wid][q + 16] = plo[1];
            red[buf][wid][q + 24] = phi[1];
        }
        __syncthreads();
        #pragma unroll
        for (int mf = 0; mf < 2; mf++) {
            const int rlo = mf * 16 + q;
            float slo = 0.0f, shi = 0.0f;
            #pragma unroll
            for (int w = 0; w < 8; w++) {
                slo += red[buf][w][rlo];
                shi += red[buf][w][rlo + 8];
            }
            const float dlo = av[it] * slo * INVH;
            const float dhi = av[it] * shi * INVH;
            #pragma unroll
            for (int f = 0; f < 4; f++) {
                xt[mf][f][0] = fmaxf(xt[mf][f][0] - dlo, 0.0f);
                xt[mf][f][1] = fmaxf(xt[mf][f][1] - dlo, 0.0f);
                xt[mf][f][2] = fmaxf(xt[mf][f][2] - dhi, 0.0f);
                xt[mf][f][3] = fmaxf(xt[mf][f][3] - dhi, 0.0f);
            }
        }
    }
    __syncthreads();

    float s[2][4][4];
    float sumlo[2] = {0, 0}, sumhi[2] = {0, 0};
    float sqlo[2]  = {0, 0}, sqhi[2]  = {0, 0};
    #pragma unroll
    for (int mf = 0; mf < 2; mf++)
        #pragma unroll
        for (int f = 0; f < 4; f++) {
            s[mf][f][0] = sc[f].x * xt[mf][f][0] * vv[mf][f][0];
            s[mf][f][1] = sc[f].y * xt[mf][f][1] * vv[mf][f][1];
            s[mf][f][2] = sc[f].x * xt[mf][f][2] * vv[mf][f][2];
            s[mf][f][3] = sc[f].y * xt[mf][f][3] * vv[mf][f][3];
            sumlo[mf] += s[mf][f][0] + s[mf][f][1];
            sumhi[mf] += s[mf][f][2] + s[mf][f][3];
            sqlo[mf]  += s[mf][f][0] * s[mf][f][0] + s[mf][f][1] * s[mf][f][1];
            sqhi[mf]  += s[mf][f][2] * s[mf][f][2] + s[mf][f][3] * s[mf][f][3];
        }
    #pragma unroll
    for (int off = 1; off <= 2; off <<= 1) {
        #pragma unroll
        for (int mf = 0; mf < 2; mf++) {
            sumlo[mf] += __shfl_xor_sync(0xffffffffu, sumlo[mf], off);
            sumhi[mf] += __shfl_xor_sync(0xffffffffu, sumhi[mf], off);
            sqlo[mf]  += __shfl_xor_sync(0xffffffffu, sqlo[mf],  off);
            sqhi[mf]  += __shfl_xor_sync(0xffffffffu, sqhi[mf],  off);
        }
    }
    if ((lane & 3) == 0) {
        red[0][wid][q]      = sumlo[0];
        red[0][wid][q + 8]  = sumhi[0];
        red[0][wid][q + 16] = sumlo[1];
        red[0][wid][q + 24] = sumhi[1];
        red[1][wid][q]      = sqlo[0];
        red[1][wid][q + 8]  = sqhi[0];
        red[1][wid][q + 16] = sqlo[1];
        red[1][wid][q + 24] = sqhi[1];
    }
    __syncthreads();

    #pragma unroll
    for (int mf = 0; mf < 2; mf++) {
        const int rlo = mf * 16 + q;
        float slo = 0, shi = 0, qlo = 0, qhi = 0;
        #pragma unroll
        for (int w = 0; w < 8; w++) {
            slo += red[0][w][rlo];   shi += red[0][w][rlo + 8];
            qlo += red[1][w][rlo];   qhi += red[1][w][rlo + 8];
        }
        const float mulo = slo * INVH;
        const float muhi = shi * INVH;
        const float ilo  = rsqrtf(fmaxf(qlo * INVH - mulo * mulo, 0.0f) + EPSq);
        const float ihi  = rsqrtf(fmaxf(qhi * INVH - muhi * muhi, 0.0f) + EPSq);

        const int row_lo = b0 + mf * 16 + q;
        float* olo = out + ((size_t)row_lo * Tq + tok) * Hq;
        float* ohi = olo + (size_t)8 * Tq * Hq;
        #pragma unroll
        for (int f = 0; f < 4; f++) {
            const int col = wid * 32 + f * 8 + 2 * (lane & 3);
            float2 v0, v1;
            v0.x = (s[mf][f][0] - mulo) * ilo * gm[f].x + bt[f].x;
            v0.y = (s[mf][f][1] - mulo) * ilo * gm[f].y + bt[f].y;
            v1.x = (s[mf][f][2] - muhi) * ihi * gm[f].x + bt[f].x;
            v1.y = (s[mf][f][3] - muhi) * ihi * gm[f].y + bt[f].y;
            *reinterpret_cast<float2*>(olo + col) = v0;
            *reinterpret_cast<float2*>(ohi + col) = v1;
        }
    }
}

// ---------------- host launch ----------------
extern "C" void kernel_launch(void* const* d_in, const int* in_sizes, int n_in,
                              void* d_out, int out_size) {
    const float* x      = (const float*)d_in[0];
    const float* w_in   = (const float*)d_in[1];
    const float* w_val  = (const float*)d_in[2];
    const float* alphas = (const float*)d_in[3];
    const float* scales = (const float*)d_in[4];
    const float* gamma  = (const float*)d_in[5];
    const float* beta   = (const float*)d_in[6];
    float* out = (float*)d_out;

    convert_a_kernel<<<1024, 256>>>(x);
    convert_b_kernel<<<8192, 256>>>(w_in, w_val);

    dim3 grid(Bq / 32, Tq);
    gemm_fused_kernel<<<grid, 256>>>(alphas, scales, gamma, beta, out);
}

// round 10
// speedup vs baseline: 1.1322x; 1.1322x over previous
#include <cuda_runtime.h>
#include <cuda_fp16.h>
#include <cstdint>

// ---------------- problem constants ----------------
constexpr int Bq = 4096;
constexpr int Eq = 512;   // K
constexpr int Tq = 32;
constexpr int Hq = 256;
constexpr int ITq = 5;
#define EPSq 1e-6f

// ---------------- fragment-ready scratch ----------------
// A frags: [mtile32 128][ks 32][mfrag 2][lane 32][8 halves]       = 4 MB
// B frags: [tok 32][ks 32][warp 8][fpair 4][lane 32][8 halves]    = 16 MB
__device__ __align__(256) __half g_xa[(size_t)128 * 32 * 2 * 32 * 8];
__device__ __align__(256) __half g_xb[(size_t)32 * 32 * 8 * 4 * 32 * 8];

__device__ __forceinline__ void mma16816(float* d, const uint32_t* a,
                                         const uint32_t* b) {
    asm volatile(
        "mma.sync.aligned.m16n8k16.row.col.f32.f16.f16.f32 "
        "{%0,%1,%2,%3},{%4,%5,%6,%7},{%8,%9},{%0,%1,%2,%3};"
        : "+f"(d[0]), "+f"(d[1]), "+f"(d[2]), "+f"(d[3])
        : "r"(a[0]), "r"(a[1]), "r"(a[2]), "r"(a[3]), "r"(b[0]), "r"(b[1]));
}

// ---------------- kernel 1: fused conversions ----------------
// blocks [0,1024):     x -> A fragments
// blocks [1024,9216):  w -> B fragments (paired layout)
__global__ __launch_bounds__(256)
void convert_kernel(const float* __restrict__ x,
                    const float* __restrict__ w_in,
                    const float* __restrict__ w_val) {
    __shared__ float tile[32][33];
    if (blockIdx.x < 1024) {
        const int idx   = blockIdx.x * 256 + threadIdx.x;
        const int lane  = idx & 31;
        const int mfrag = (idx >> 5) & 1;
        const int ks    = (idx >> 6) & 31;
        const int mtile = idx >> 11;
        const int r0 = mtile * 32 + mfrag * 16 + (lane >> 2);
        const int c0 = ks * 16 + 2 * (lane & 3);
        const float* xr0 = x + (size_t)r0 * Eq;
        const float* xr1 = xr0 + 8 * Eq;
        __half h[8];
        h[0] = __float2half_rn(xr0[c0]);     h[1] = __float2half_rn(xr0[c0 + 1]);
        h[2] = __float2half_rn(xr1[c0]);     h[3] = __float2half_rn(xr1[c0 + 1]);
        h[4] = __float2half_rn(xr0[c0 + 8]); h[5] = __float2half_rn(xr0[c0 + 9]);
        h[6] = __float2half_rn(xr1[c0 + 8]); h[7] = __float2half_rn(xr1[c0 + 9]);
        reinterpret_cast<uint4*>(g_xa)[idx] = *reinterpret_cast<uint4*>(h);
        return;
    }
    const int bz = blockIdx.x - 1024;       // 0..8191
    const int e0 = (bz & 15) * 32;
    const int h0 = ((bz >> 4) & 7) * 32;
    const int z  = bz >> 7;
    const int m  = z >> 5;
    const int t  = z & 31;
    const float* src = (m ? w_val : w_in) + (size_t)t * Eq * Hq;
    const int tx = threadIdx.x & 31;
    const int ty = threadIdx.x >> 5;
    #pragma unroll
    for (int r = ty; r < 32; r += 8)
        tile[r][tx] = src[(size_t)(e0 + r) * Hq + h0 + tx];
    __syncthreads();
    const int lane = threadIdx.x & 31;
    const int f    = (threadIdx.x >> 5) & 3;
    const int ksl  = threadIdx.x >> 7;            // 0/1
    const int ks   = (e0 >> 4) + ksl;
    const int k0   = ksl * 16 + 2 * (lane & 3);
    const int hc   = f * 8 + (lane >> 2);
    const int wp   = h0 >> 5;
    const int fi   = f + m * 4;                   // 0..7
    __half hv[4];
    hv[0] = __float2half_rn(tile[k0][hc]);
    hv[1] = __float2half_rn(tile[k0 + 1][hc]);
    hv[2] = __float2half_rn(tile[k0 + 8][hc]);
    hv[3] = __float2half_rn(tile[k0 + 9][hc]);
    // paired layout: [t][ks][wp][fi>>1][lane] 16B, half (fi&1) selects 8B
    const size_t di = (((((size_t)t * 32 + ks) * 8 + wp) * 4 + (fi >> 1)) * 32
                      + lane) * 2 + (fi & 1);
    reinterpret_cast<uint2*>(g_xb)[di] = *reinterpret_cast<uint2*>(hv);
}

// ---------------- kernel 2: all-LDG register GEMM + fused epilogue ----------
__global__ __launch_bounds__(256, 2)
void gemm_fused_kernel(const float* __restrict__ alphas,
                       const float* __restrict__ scales,
                       const float* __restrict__ gamma,
                       const float* __restrict__ beta,
                       float* __restrict__ out)
{
    __shared__ float red[2][8][32];

    const int tid  = threadIdx.x;
    const int wid  = tid >> 5;
    const int lane = tid & 31;
    const int mtile = blockIdx.x;   // 0..127
    const int tok   = blockIdx.y;   // 0..31
    const int b0    = mtile * 32;

    const uint4* pa = reinterpret_cast<const uint4*>(g_xa)
                    + ((size_t)mtile * 32) * 2 * 32 + lane;
    const uint4* pb = reinterpret_cast<const uint4*>(g_xb)
                    + (((size_t)tok * 32) * 8 + wid) * 4 * 32 + lane;

    float acc[2][8][4];
    #pragma unroll
    for (int i = 0; i < 2; i++)
        #pragma unroll
        for (int j = 0; j < 8; j++)
            #pragma unroll
            for (int k = 0; k < 4; k++) acc[i][j][k] = 0.0f;

    uint4 a0[2], a1[2];
    uint4 bb0[4], bb1[4];

    #define LOAD_A(ks, A) do {                                   \
        A[0] = pa[(size_t)(ks) * 64];                            \
        A[1] = pa[(size_t)(ks) * 64 + 32];                       \
    } while (0)
    #define LOAD_B(ks, BB) do {                                  \
        _Pragma("unroll")                                        \
        for (int j = 0; j < 4; j++)                              \
            BB[j] = pb[(size_t)(ks) * 1024 + j * 32];            \
    } while (0)
    #define DO_MMA(A, BB) do {                                   \
        _Pragma("unroll")                                        \
        for (int mf = 0; mf < 2; mf++)                           \
            _Pragma("unroll")                                    \
            for (int f = 0; f < 8; f++)                          \
                mma16816(acc[mf][f],                             \
                         reinterpret_cast<const uint32_t*>(&A[mf]), \
                         reinterpret_cast<const uint32_t*>(&BB[f >> 1]) + (f & 1) * 2); \
    } while (0)

    LOAD_A(0, a0); LOAD_B(0, bb0);
    #pragma unroll
    for (int ks = 0; ks < 32; ks += 2) {
        if (ks + 1 < 32) { LOAD_A(ks + 1, a1); LOAD_B(ks + 1, bb1); }
        DO_MMA(a0, bb0);
        if (ks + 2 < 32) { LOAD_A(ks + 2, a0); LOAD_B(ks + 2, bb0); }
        if (ks + 1 < 32) DO_MMA(a1, bb1);
    }

    // ---------------- epilogue (register-resident gating) ----------------
    float xt[2][4][4], vv[2][4][4];
    #pragma unroll
    for (int mf = 0; mf < 2; mf++)
        #pragma unroll
        for (int f = 0; f < 4; f++)
            #pragma unroll
            for (int c = 0; c < 4; c++) {
                xt[mf][f][c] = fmaxf(acc[mf][f][c], 0.0f);
                vv[mf][f][c] = acc[mf][f + 4][c];
            }

    float av[ITq];
    #pragma unroll
    for (int i = 0; i < ITq; i++) av[i] = alphas[tok * ITq + i];

    float2 sc[4], gm[4], bt[4];
    #pragma unroll
    for (int f = 0; f < 4; f++) {
        const int col = wid * 32 + f * 8 + 2 * (lane & 3);
        sc[f] = *reinterpret_cast<const float2*>(scales + tok * Hq + col);
        gm[f] = *reinterpret_cast<const float2*>(gamma  + tok * Hq + col);
        bt[f] = *reinterpret_cast<const float2*>(beta   + tok * Hq + col);
    }

    constexpr float INVH = 1.0f / (float)Hq;
    const int q = lane >> 2;

    #pragma unroll
    for (int it = 0; it < ITq; it++) {
        float plo[2], phi[2];
        #pragma unroll
        for (int mf = 0; mf < 2; mf++) {
            plo[mf] = 0.0f; phi[mf] = 0.0f;
            #pragma unroll
            for (int f = 0; f < 4; f++) {
                plo[mf] += xt[mf][f][0] + xt[mf][f][1];
                phi[mf] += xt[mf][f][2] + xt[mf][f][3];
            }
        }
        #pragma unroll
        for (int off = 1; off <= 2; off <<= 1) {
            #pragma unroll
            for (int mf = 0; mf < 2; mf++) {
                plo[mf] += __shfl_xor_sync(0xffffffffu, plo[mf], off);
                phi[mf] += __shfl_xor_sync(0xffffffffu, phi[mf], off);
            }
        }
        const int buf = it & 1;
        if ((lane & 3) == 0) {
            red[buf][wid][q]      = plo[0];
            red[buf][wid][q + 8]  = phi[0];
            red[buf][wid][q + 16] = plo[1];
            red[buf][wid][q + 24] = phi[1];
        }
        __syncthreads();
        #pragma unroll
        for (int mf = 0; mf < 2; mf++) {
            const int rlo = mf * 16 + q;
            float slo = 0.0f, shi = 0.0f;
            #pragma unroll
            for (int w = 0; w < 8; w++) {
                slo += red[buf][w][rlo];
                shi += red[buf][w][rlo + 8];
            }
            const float dlo = av[it] * slo * INVH;
            const float dhi = av[it] * shi * INVH;
            #pragma unroll
            for (int f = 0; f < 4; f++) {
                xt[mf][f][0] = fmaxf(xt[mf][f][0] - dlo, 0.0f);
                xt[mf][f][1] = fmaxf(xt[mf][f][1] - dlo, 0.0f);
                xt[mf][f][2] = fmaxf(xt[mf][f][2] - dhi, 0.0f);
                xt[mf][f][3] = fmaxf(xt[mf][f][3] - dhi, 0.0f);
            }
        }
    }
    __syncthreads();

    float s[2][4][4];
    float sumlo[2] = {0, 0}, sumhi[2] = {0, 0};
    float sqlo[2]  = {0, 0}, sqhi[2]  = {0, 0};
    #pragma unroll
    for (int mf = 0; mf < 2; mf++)
        #pragma unroll
        for (int f = 0; f < 4; f++) {
            s[mf][f][0] = sc[f].x * xt[mf][f][0] * vv[mf][f][0];
            s[mf][f][1] = sc[f].y * xt[mf][f][1] * vv[mf][f][1];
            s[mf][f][2] = sc[f].x * xt[mf][f][2] * vv[mf][f][2];
            s[mf][f][3] = sc[f].y * xt[mf][f][3] * vv[mf][f][3];
            sumlo[mf] += s[mf][f][0] + s[mf][f][1];
            sumhi[mf] += s[mf][f][2] + s[mf][f][3];
            sqlo[mf]  += s[mf][f][0] * s[mf][f][0] + s[mf][f][1] * s[mf][f][1];
            sqhi[mf]  += s[mf][f][2] * s[mf][f][2] + s[mf][f][3] * s[mf][f][3];
        }
    #pragma unroll
    for (int off = 1; off <= 2; off <<= 1) {
        #pragma unroll
        for (int mf = 0; mf < 2; mf++) {
            sumlo[mf] += __shfl_xor_sync(0xffffffffu, sumlo[mf], off);
            sumhi[mf] += __shfl_xor_sync(0xffffffffu, sumhi[mf], off);
            sqlo[mf]  += __shfl_xor_sync(0xffffffffu, sqlo[mf],  off);
            sqhi[mf]  += __shfl_xor_sync(0xffffffffu, sqhi[mf],  off);
        }
    }
    if ((lane & 3) == 0) {
        red[0][wid][q]      = sumlo[0];
        red[0][wid][q + 8]  = sumhi[0];
        red[0][wid][q + 16] = sumlo[1];
        red[0][wid][q + 24] = sumhi[1];
        red[1][wid][q]      = sqlo[0];
        red[1][wid][q + 8]  = sqhi[0];
        red[1][wid][q + 16] = sqlo[1];
        red[1][wid][q + 24] = sqhi[1];
    }
    __syncthreads();

    #pragma unroll
    for (int mf = 0; mf < 2; mf++) {
        const int rlo = mf * 16 + q;
        float slo = 0, shi = 0, qlo = 0, qhi = 0;
        #pragma unroll
        for (int w = 0; w < 8; w++) {
            slo += red[0][w][rlo];   shi += red[0][w][rlo + 8];
            qlo += red[1][w][rlo];   qhi += red[1][w][rlo + 8];
        }
        const float mulo = slo * INVH;
        const float muhi = shi * INVH;
        const float ilo  = rsqrtf(fmaxf(qlo * INVH - mulo * mulo, 0.0f) + EPSq);
        const float ihi  = rsqrtf(fmaxf(qhi * INVH - muhi * muhi, 0.0f) + EPSq);

        const int row_lo = b0 + mf * 16 + q;
        float* olo = out + ((size_t)row_lo * Tq + tok) * Hq;
        float* ohi = olo + (size_t)8 * Tq * Hq;
        #pragma unroll
        for (int f = 0; f < 4; f++) {
            const int col = wid * 32 + f * 8 + 2 * (lane & 3);
            float2 v0, v1;
            v0.x = (s[mf][f][0] - mulo) * ilo * gm[f].x + bt[f].x;
            v0.y = (s[mf][f][1] - mulo) * ilo * gm[f].y + bt[f].y;
            v1.x = (s[mf][f][2] - muhi) * ihi * gm[f].x + bt[f].x;
            v1.y = (s[mf][f][3] - muhi) * ihi * gm[f].y + bt[f].y;
            *reinterpret_cast<float2*>(olo + col) = v0;
            *reinterpret_cast<float2*>(ohi + col) = v1;
        }
    }
}

// ---------------- host launch ----------------
extern "C" void kernel_launch(void* const* d_in, const int* in_sizes, int n_in,
                              void* d_out, int out_size) {
    const float* x      = (const float*)d_in[0];
    const float* w_in   = (const float*)d_in[1];
    const float* w_val  = (const float*)d_in[2];
    const float* alphas = (const float*)d_in[3];
    const float* scales = (const float*)d_in[4];
    const float* gamma  = (const float*)d_in[5];
    const float* beta   = (const float*)d_in[6];
    float* out = (float*)d_out;

    convert_kernel<<<1024 + 8192, 256>>>(x, w_in, w_val);

    dim3 grid(Bq / 32, Tq);
    gemm_fused_kernel<<<grid, 256>>>(alphas, scales, gamma, beta, out);
}